// round 17
// baseline (speedup 1.0000x reference)
#include <cuda_runtime.h>
#include <math.h>

#define BB     4096
#define LMAX   5
#define TMAX   50
#define BPB    32                     // batches per block (2 per warp)
#define NBLK   (BB / BPB)             // 128 blocks
#define NTHR   512                    // 16 warps
#define NV4    ((BPB * TMAX) / 4)     // 400 float4 loads per block
#define NWV    ((NV4 + 31) / 32)      // 13 warps carry trg partials
#define LOG_CT (-3.8918202981106265f) // log(1/49)
#define Q20    1048576.0              // 2^20 fixed-point scale
#define BIAS   4294967296ll           // 2^32 per-block bias (keeps packed field >= 0)

// Packed accumulator: bits[0:8) = arrival count, bits[8:64) = sum of biased Q20 partials.
__device__ unsigned long long g_acc = 0ull;

// Closed form (softmax row sums == 1; P_st = 1/49):
//   M = sum(mask), Q = sum(mask^2), Linv = 1/max(M,1)
//   scales: t=0 -> ct*Linv*M ; t>=1 -> ct*Linv*Q   (recursion fixed point)
//   ll = log(1/49) * sum(trg_boundary)              (Z = M/M == 1 exactly)
__global__ __launch_bounds__(NTHR, 2)
void mixalign_kernel(const float* __restrict__ src_bd,   // [B, L]
                     const float* __restrict__ trg_bd,   // [B, T]
                     float* __restrict__ out)            // [1 + B*T]
{
    const int tid  = threadIdx.x;
    const int w    = tid >> 5;
    const int lane = tid & 31;
    const int b0   = blockIdx.x * BPB + w * 2;   // this warp's first batch

    __shared__ float sWp[NWV];

    // ---- trg_bd slice: 400 float4 loads (warps 0..12), issued first for MLP ----
    float v = 0.f;
    if (tid < NV4) {
        const float4 t4 =
            ((const float4*)(trg_bd + (size_t)blockIdx.x * (BPB * TMAX)))[tid];
        v = (t4.x + t4.y) + (t4.z + t4.w);
    }

    // ---- two batches per warp: same-address broadcast loads, no shuffles ----
    const float ct = 1.0f / 49.0f;
    const float* mrow = src_bd + (size_t)b0 * LMAX;

    const float a0 = mrow[0], a1 = mrow[1], a2 = mrow[2], a3 = mrow[3], a4 = mrow[4];
    const float c0 = mrow[5], c1 = mrow[6], c2 = mrow[7], c3 = mrow[8], c4 = mrow[9];

    const float Ma = ((a0 + a1) + (a2 + a3)) + a4;
    const float Qa = ((a0 * a0 + a1 * a1) + (a2 * a2 + a3 * a3)) + a4 * a4;
    const float Mb = ((c0 + c1) + (c2 + c3)) + c4;
    const float Qb = ((c0 * c0 + c1 * c1) + (c2 * c2 + c3 * c3)) + c4 * c4;

    const float La = __fdividef(1.f, fmaxf(Ma, 1.f));
    const float Lb = __fdividef(1.f, fmaxf(Mb, 1.f));
    const float s0a = ct * (La * Ma), scca = ct * (La * Qa);
    const float s0b = ct * (Lb * Mb), sccb = ct * (Lb * Qb);

    // ---- scale stores (coalesced within warp), 2 batches x 50 floats ----
    float* ob = out + 1 + (size_t)b0 * TMAX;
    ob[lane] = lane ? scca : s0a;
    if (lane + 32 < TMAX) ob[lane + 32] = scca;
    ob[TMAX + lane] = lane ? sccb : s0b;
    if (lane + 32 < TMAX) ob[TMAX + lane + 32] = sccb;

    // ---- trg partial: warp reduce (warps 0..12 only), then 13-wide final ----
    if (w < NWV) {
        #pragma unroll
        for (int o = 16; o; o >>= 1) v += __shfl_xor_sync(0xFFFFFFFFu, v, o);
        if (lane == 0) sWp[w] = v;
    }
    __syncthreads();

    if (w == 0) {
        float x = (lane < NWV) ? sWp[lane] : 0.f;
        #pragma unroll
        for (int o = 8; o; o >>= 1) x += __shfl_xor_sync(0xFFFFFFFFu, x, o);
        if (lane == 0) {
            // ONE atomic per block: counter in low 8 bits, biased Q20 sum above.
            const long long qb = (long long)llrint((double)x * Q20) + BIAS;
            const unsigned long long pack = ((unsigned long long)qb << 8) | 1ull;
            const unsigned long long old  = atomicAdd(&g_acc, pack);
            if ((old & 0xFFull) == (unsigned long long)(NBLK - 1)) {
                // last arrival: old+pack holds the complete packed total
                const long long tot = (long long)((old + pack) >> 8) - (long long)NBLK * BIAS;
                out[0] = (float)((double)tot * (1.0 / Q20)) * LOG_CT;
                g_acc = 0ull;                 // reset for next graph replay
            }
        }
    }
}

extern "C" void kernel_launch(void* const* d_in, const int* in_sizes, int n_in,
                              void* d_out, int out_size)
{
    const float* src_bd = (const float*)d_in[2];  // [B, L]
    const float* trg_bd = (const float*)d_in[3];  // [B, T]
    float* out = (float*)d_out;                   // [1 + B*T]

    mixalign_kernel<<<NBLK, NTHR>>>(src_bd, trg_bd, out);
}